// round 7
// baseline (speedup 1.0000x reference)
#include <cuda_runtime.h>

// LTC RNN, B=256 T=8192 I=6 U=64 M=16, 6 ODE unfolds.
// Round-7 = Round-6 with the sensory-constant bug fixed (dsa/nsa must be
// initialized with sCd/sCn — the constant halves of sigmoid=0.5+0.5tanh).
// All-f32; 4-way j-split: 256 thr/CTA, 8 warps; warp owns 8 units, lane
// quarter r=lane>>3 covers j in [16r,16r+16). Per-warp MUFU burst 16,
// accumulator chains 8-deep, reduce = shfl.bfly(8)+bfly(16). 2 co-resident
// CTAs = 4 warps/SMSP hide each other's per-unfold serial tails.
// v ping-pong smem padded v[j] -> j + 2*(j>>4). 1 barrier per unfold.

#define T_LEN 8192
#define NI 6
#define NU 64
#define NM 16

static __device__ __forceinline__ float fast_tanh(float x) {
    float r; asm("tanh.approx.f32 %0, %1;" : "=f"(r) : "f"(x)); return r;
}
static __device__ __forceinline__ float fabs_bits(float v) {
    return __int_as_float(__float_as_int(v) & 0x7fffffff);
}

__global__ __launch_bounds__(256, 2)
void ltc_kernel(const float* __restrict__ x,
                const float* __restrict__ gleak,
                const float* __restrict__ vleak,
                const float* __restrict__ cm,
                const float* __restrict__ sigma,
                const float* __restrict__ mu,
                const float* __restrict__ w,
                const float* __restrict__ erev,
                const float* __restrict__ s_sigma,
                const float* __restrict__ s_mu,
                const float* __restrict__ s_w,
                const float* __restrict__ s_erev,
                const float* __restrict__ in_w,
                const float* __restrict__ in_b,
                const float* __restrict__ out_w,
                const float* __restrict__ out_b,
                float* __restrict__ out)
{
    __shared__ __align__(8) float vsm[2][72];   // v[j] at j + 2*(j>>4)

    const int b    = blockIdx.x;
    const int tid  = threadIdx.x;
    const int lane = tid & 31;
    const int wrp  = tid >> 5;                  // 0..7
    const int r    = lane >> 3;                 // j-quarter 0..3
    const int u    = (wrp << 3) | (lane & 7);   // unit 0..63
    const int rbase = 18 * r;                   // padded read base (words)

    const float gl   = gleak[u];
    const float cmt  = cm[u] * 6.0f;
    const float glvl = gl * vleak[u];
    const float denc = cmt + gl + 1e-8f;

    // 16 per-(j,u) constants in registers
    float cs[16], cc[16], we[16];
    float Cd = 0.f, Cn = 0.f;
#pragma unroll
    for (int jj = 0; jj < 16; jj++) {
        int j   = 16 * r + jj;
        int idx = j * NU + u;
        float s = 0.5f * sigma[idx];
        cs[jj]  = s;
        cc[jj]  = -mu[idx] * s;
        float wv = 0.5f * w[idx] * erev[idx];
        we[jj]  = wv;
        Cd += fabsf(wv);
        Cn += wv;
    }

    // sensory: quarters 0..2 take inputs (2r, 2r+1); quarter 3 contributes 0
    const int  ii0   = (r < 3) ? 2 * r : 0;
    const bool sact  = (r < 3);
    float ss0, sc0, sw0, ss1, sc1, sw1, iw0, ib0, iw1, ib1;
    float sCd, sCn;
    {
        int i0 = ii0 * NU + u, i1 = (ii0 + 1) * NU + u;
        float a0 = 0.5f * s_sigma[i0], a1 = 0.5f * s_sigma[i1];
        ss0 = a0; sc0 = -s_mu[i0] * a0;
        ss1 = a1; sc1 = -s_mu[i1] * a1;
        float w0 = sact ? 0.5f * s_w[i0] * s_erev[i0] : 0.f;
        float w1 = sact ? 0.5f * s_w[i1] * s_erev[i1] : 0.f;
        sw0 = w0; sw1 = w1;
        sCd = fabsf(w0) + fabsf(w1);
        sCn = w0 + w1;
        iw0 = in_w[ii0]; ib0 = in_b[ii0];
        iw1 = in_w[ii0 + 1]; ib1 = in_b[ii0 + 1];
    }

    float ow = 0.f, ob = 0.f;
    if (u < NM) { ow = out_w[u]; ob = out_b[u]; }
    const bool do_out = (u < NM) && (r == 0);

    if (r == 0) vsm[0][u + 2 * (u >> 4)] = 0.f;
    float vu = 0.f;

    const float* xb = x + (long long)b * T_LEN * NI + ii0;
    float2 xr = *reinterpret_cast<const float2*>(xb);
    float* outp = out + (long long)b * T_LEN * NM;

    // anti-phase stagger for the co-resident partner CTA (classic placement
    // maps bid and bid+148 to one SM): desynchronize per-unfold tails.
    if (b >= 148) {
        float d = (float)tid * 1.0e-3f;
#pragma unroll
        for (int i = 0; i < 24; i++)
            asm volatile("tanh.approx.f32 %0, %0;" : "+f"(d));
    }

    __syncthreads();

    for (int t = 0; t < T_LEN; t++) {
        float x0 = xr.x, x1 = xr.y;
        if (t + 1 < T_LEN)
            xr = *reinterpret_cast<const float2*>(xb + (size_t)(t + 1) * NI);

        // sensory synapses (constant across the 6 unfolds).
        // NOTE: accumulators MUST start at sCd/sCn (constant half of
        // sigmoid = 0.5 + 0.5*tanh) — dropping them was the round-6 bug.
        float xi0 = fmaf(x0, iw0, ib0);
        float xi1 = fmaf(x1, iw1, ib1);
        float h0 = fast_tanh(fmaf(xi0, ss0, sc0));
        float h1 = fast_tanh(fmaf(xi1, ss1, sc1));
        float dsa = fmaf(fabs_bits(sw0), h0, fmaf(fabs_bits(sw1), h1, sCd));
        float nsa = fmaf(sw0, h0, fmaf(sw1, h1, sCn));
        dsa += __shfl_xor_sync(0xffffffffu, dsa, 8);
        nsa += __shfl_xor_sync(0xffffffffu, nsa, 8);
        dsa += __shfl_xor_sync(0xffffffffu, dsa, 16);
        nsa += __shfl_xor_sync(0xffffffffu, nsa, 16);
        float den_b = denc + dsa;
        float num_b = glvl + nsa;

        // 6 semi-implicit Euler unfolds, ping-pong v buffers
#pragma unroll 2
        for (int k = 0; k < 6; k++) {
            const float* vr = &vsm[k & 1][rbase];
            float an0 = Cn, ad0 = Cd, an1 = 0.f, ad1 = 0.f;
#pragma unroll
            for (int p = 0; p < 8; p++) {
                float2 vp = *reinterpret_cast<const float2*>(vr + 2 * p);
                float ha = fast_tanh(fmaf(vp.x, cs[2*p],   cc[2*p]));
                float hb = fast_tanh(fmaf(vp.y, cs[2*p+1], cc[2*p+1]));
                float wa = we[2*p], wb = we[2*p+1];
                an0 = fmaf(wa, ha, an0);  ad0 = fmaf(fabs_bits(wa), ha, ad0);
                an1 = fmaf(wb, hb, an1);  ad1 = fmaf(fabs_bits(wb), hb, ad1);
            }
            float an = an0 + an1, ad = ad0 + ad1;
            an += __shfl_xor_sync(0xffffffffu, an, 8);
            ad += __shfl_xor_sync(0xffffffffu, ad, 8);
            an += __shfl_xor_sync(0xffffffffu, an, 16);
            ad += __shfl_xor_sync(0xffffffffu, ad, 16);
            float num = fmaf(cmt, vu, num_b + an);
            vu = __fdividef(num, den_b + ad);
            if (r == 0) vsm[(k & 1) ^ 1][u + 2 * (u >> 4)] = vu;
            __syncthreads();
        }

        if (do_out) outp[(size_t)t * NM + u] = fmaf(vu, ow, ob);
    }
}

extern "C" void kernel_launch(void* const* d_in, const int* in_sizes, int n_in,
                              void* d_out, int out_size) {
    (void)in_sizes; (void)n_in; (void)out_size;
    ltc_kernel<<<256, 256>>>(
        (const float*)d_in[0],  (const float*)d_in[1],  (const float*)d_in[2],
        (const float*)d_in[3],  (const float*)d_in[4],  (const float*)d_in[5],
        (const float*)d_in[6],  (const float*)d_in[7],  (const float*)d_in[8],
        (const float*)d_in[9],  (const float*)d_in[10], (const float*)d_in[11],
        (const float*)d_in[12], (const float*)d_in[13], (const float*)d_in[14],
        (const float*)d_in[15], (float*)d_out);
}

// round 8
// speedup vs baseline: 1.1141x; 1.1141x over previous
#include <cuda_runtime.h>

// LTC RNN, B=256 T=8192 I=6 U=64 M=16, 6 ODE unfolds. MUFU-bound (78% at
// round-1 structure; fma full-rate on sm_100a has big headroom).
// Round-8 = round-1 structure + anti-phase CTA stagger + LDS.128 + 4 chains.
//   Two co-resident CTAs (classic placement pairs bid and bid+148) have two
//   equilibria: in-phase (both burst at half MUFU rate, then idle through
//   tails together; period~660 = measured) and anti-phase (period 512, 100%
//   MUFU). One-time ~320cyc delay on the bid>=148 partner selects anti-phase.
// Layout: 1 CTA/batch, 128 thr; warp w owns units [16w,16w+16); lane half
// q=lane/16 covers j in [32q,32q+32). Constants in registers. v ping-pong
// f32 smem padded v[j] -> j+4*(j>>5) (float4 reads, conflict-free).

#define T_LEN 8192
#define NI 6
#define NU 64
#define NM 16

static __device__ __forceinline__ float fast_tanh(float x) {
    float r; asm("tanh.approx.f32 %0, %1;" : "=f"(r) : "f"(x)); return r;
}
static __device__ __forceinline__ float fabs_bits(float v) {
    return __int_as_float(__float_as_int(v) & 0x7fffffff);
}

__global__ __launch_bounds__(128, 2)
void ltc_kernel(const float* __restrict__ x,
                const float* __restrict__ gleak,
                const float* __restrict__ vleak,
                const float* __restrict__ cm,
                const float* __restrict__ sigma,
                const float* __restrict__ mu,
                const float* __restrict__ w,
                const float* __restrict__ erev,
                const float* __restrict__ s_sigma,
                const float* __restrict__ s_mu,
                const float* __restrict__ s_w,
                const float* __restrict__ s_erev,
                const float* __restrict__ in_w,
                const float* __restrict__ in_b,
                const float* __restrict__ out_w,
                const float* __restrict__ out_b,
                float* __restrict__ out)
{
    __shared__ __align__(16) float vsm[2][72];  // v[j] at j + 4*(j>>5)

    const int b    = blockIdx.x;
    const int tid  = threadIdx.x;
    const int lane = tid & 31;
    const int wrp  = tid >> 5;
    const int q    = lane >> 4;               // j-half selector
    const int u    = (wrp << 4) | (lane & 15);
    const int rbase = 36 * q;                 // padded read base (16B-aligned)

    const float gl   = gleak[u];
    const float cmt  = cm[u] * 6.0f;
    const float glvl = gl * vleak[u];
    const float denc = cmt + gl + 1e-8f;

    // 32 per-(j,u) constants in registers
    float cs[32], cc[32], we[32];
    float Cd = 0.f, Cn = 0.f;
#pragma unroll
    for (int jj = 0; jj < 32; jj++) {
        int j   = 32 * q + jj;
        int idx = j * NU + u;
        float s = 0.5f * sigma[idx];
        cs[jj]  = s;
        cc[jj]  = -mu[idx] * s;
        float wv = 0.5f * w[idx] * erev[idx];
        we[jj]  = wv;
        Cd += fabsf(wv);
        Cn += wv;
    }

    // sensory constants: lane half q handles inputs [3q, 3q+3)
    float ss[3], sc2[3], swe[3], iw[3], ib[3];
    float sCd = 0.f, sCn = 0.f;
#pragma unroll
    for (int i = 0; i < 3; i++) {
        int ii  = 3 * q + i;
        int idx = ii * NU + u;
        float s = 0.5f * s_sigma[idx];
        ss[i]   = s;
        sc2[i]  = -s_mu[idx] * s;
        float wv = 0.5f * s_w[idx] * s_erev[idx];
        swe[i]  = wv;
        sCd += fabsf(wv);
        sCn += wv;
        iw[i] = in_w[ii];
        ib[i] = in_b[ii];
    }

    float ow = 0.f, ob = 0.f;
    if (tid < NM) { ow = out_w[tid]; ob = out_b[tid]; }

    if (q == 0) vsm[0][u + 4 * (u >> 5)] = 0.f;
    float vu = 0.f;

    const float* xb = x + (long long)b * T_LEN * NI + 3 * q;
    float xr0 = xb[0], xr1 = xb[1], xr2 = xb[2];
    float* outp = out + (long long)b * T_LEN * NM;

    // One-time anti-phase stagger: the co-resident partner (bid>=148 under
    // classic placement) is delayed ~320cyc (20 dependent MUFU) so the two
    // CTAs settle into the anti-phase equilibrium (one bursts while the
    // other drains its per-unfold serial tail) instead of in-phase lock.
    if (b >= 148) {
        float d = (float)(tid + 1) * 1.0e-3f;
#pragma unroll
        for (int i = 0; i < 20; i++)
            asm volatile("tanh.approx.f32 %0, %0;" : "+f"(d));
        // keep d alive without affecting results
        if (d > 2.0f) vsm[1][70] = d;   // never true (|tanh|<1)
    }

    __syncthreads();

    for (int t = 0; t < T_LEN; t++) {
        float x0 = xr0, x1 = xr1, x2 = xr2;
        if (t + 1 < T_LEN) {
            const float* xn = xb + (size_t)(t + 1) * NI;
            xr0 = xn[0]; xr1 = xn[1]; xr2 = xn[2];
        }

        // sensory synapses (constant across the 6 unfolds)
        float xi0 = fmaf(x0, iw[0], ib[0]);
        float xi1 = fmaf(x1, iw[1], ib[1]);
        float xi2 = fmaf(x2, iw[2], ib[2]);
        float dsa = sCd, nsa = sCn, h;
        h = fast_tanh(fmaf(xi0, ss[0], sc2[0]));
        dsa = fmaf(fabs_bits(swe[0]), h, dsa);  nsa = fmaf(swe[0], h, nsa);
        h = fast_tanh(fmaf(xi1, ss[1], sc2[1]));
        dsa = fmaf(fabs_bits(swe[1]), h, dsa);  nsa = fmaf(swe[1], h, nsa);
        h = fast_tanh(fmaf(xi2, ss[2], sc2[2]));
        dsa = fmaf(fabs_bits(swe[2]), h, dsa);  nsa = fmaf(swe[2], h, nsa);
        dsa += __shfl_xor_sync(0xffffffffu, dsa, 16);
        nsa += __shfl_xor_sync(0xffffffffu, nsa, 16);
        float den_b = denc + dsa;
        float num_b = glvl + nsa;

        // 6 semi-implicit Euler unfolds, ping-pong v buffers
#pragma unroll
        for (int k = 0; k < 6; k++) {
            const float4* vr4 =
                reinterpret_cast<const float4*>(&vsm[k & 1][rbase]);
            float an0 = Cn, an1 = 0.f, ad0 = Cd, ad1 = 0.f;
#pragma unroll
            for (int p = 0; p < 8; p++) {
                float4 v4 = vr4[p];                        // LDS.128 broadcast
                float h0 = fast_tanh(fmaf(v4.x, cs[4*p],   cc[4*p]));
                float h1 = fast_tanh(fmaf(v4.y, cs[4*p+1], cc[4*p+1]));
                float h2 = fast_tanh(fmaf(v4.z, cs[4*p+2], cc[4*p+2]));
                float h3 = fast_tanh(fmaf(v4.w, cs[4*p+3], cc[4*p+3]));
                float w0 = we[4*p],   w1 = we[4*p+1];
                float w2 = we[4*p+2], w3 = we[4*p+3];
                an0 = fmaf(w0, h0, an0);  ad0 = fmaf(fabs_bits(w0), h0, ad0);
                an1 = fmaf(w1, h1, an1);  ad1 = fmaf(fabs_bits(w1), h1, ad1);
                an0 = fmaf(w2, h2, an0);  ad0 = fmaf(fabs_bits(w2), h2, ad0);
                an1 = fmaf(w3, h3, an1);  ad1 = fmaf(fabs_bits(w3), h3, ad1);
            }
            float an = an0 + an1, ad = ad0 + ad1;
            an += __shfl_xor_sync(0xffffffffu, an, 16);
            ad += __shfl_xor_sync(0xffffffffu, ad, 16);
            float num = fmaf(cmt, vu, num_b + an);
            vu = __fdividef(num, den_b + ad);
            if (q == 0) vsm[(k & 1) ^ 1][u + 4 * (u >> 5)] = vu;
            __syncthreads();
        }

        if (tid < NM) outp[(size_t)t * NM + tid] = fmaf(vu, ow, ob);
    }
}

extern "C" void kernel_launch(void* const* d_in, const int* in_sizes, int n_in,
                              void* d_out, int out_size) {
    (void)in_sizes; (void)n_in; (void)out_size;
    ltc_kernel<<<256, 128>>>(
        (const float*)d_in[0],  (const float*)d_in[1],  (const float*)d_in[2],
        (const float*)d_in[3],  (const float*)d_in[4],  (const float*)d_in[5],
        (const float*)d_in[6],  (const float*)d_in[7],  (const float*)d_in[8],
        (const float*)d_in[9],  (const float*)d_in[10], (const float*)d_in[11],
        (const float*)d_in[12], (const float*)d_in[13], (const float*)d_in[14],
        (const float*)d_in[15], (float*)d_out);
}

// round 9
// speedup vs baseline: 1.1682x; 1.0485x over previous
#include <cuda_runtime.h>
#include <math.h>

// LTC RNN, B=256 T=8192 I=6 U=64 M=16, 6 ODE unfolds. MUFU-bound at 630
// cyc/unfold vs 512 floor; fma 27.6%, alu 1.3% -> idle pipes.
// Round-9: offload 8 of 32 sigmoids per lane from MUFU to a piecewise-linear
// tanh LUT in smem (1024 segs over [-16,16), step 1/32, max err 9.4e-5).
// Index is cvt-free: y = x + 96 lands in binade [64,128) so the segment id
// is (bits(y)>>12)&0x7FF (FADD + SHF/LOP3 + IMAD + LDS.64 + FFMA lerp) —
// runs entirely on fma/ALU/LSU pipes. |arg| <= ~8.4 provably (LTC |v|<=1.3),
// so no clamp. Sensory tanh (unbounded arg) stays on MUFU. New balance:
// MUFU 384 cyc/SMSP-unfold vs issue ~376 -> pipes matched.
// Base structure = round-8: 1 CTA/batch, 128 thr, q-half j-split, constants
// in registers, LDS.128 v loads, ping-pong padded v smem, 1 barrier/unfold.

#define T_LEN 8192
#define NI 6
#define NU 64
#define NM 16

static __device__ __forceinline__ float fast_tanh(float x) {
    float r; asm("tanh.approx.f32 %0, %1;" : "=f"(r) : "f"(x)); return r;
}
static __device__ __forceinline__ float fabs_bits(float v) {
    return __int_as_float(__float_as_int(v) & 0x7fffffff);
}
// PWL tanh: lutm512 = (float2*)lut - 512 so idx in [512,1536) hits [0,1024)
static __device__ __forceinline__ float lut_tanh(const float2* lutm512, float x) {
    float y = x + 96.0f;                       // [80,112) c [64,128) binade
    unsigned u = __float_as_uint(y);
    unsigned idx = (u >> 12) & 0x7FFu;         // segment + 512
    float2 sb = lutm512[idx];                  // (slope, intercept)
    return fmaf(x, sb.x, sb.y);
}

__global__ __launch_bounds__(128, 2)
void ltc_kernel(const float* __restrict__ x,
                const float* __restrict__ gleak,
                const float* __restrict__ vleak,
                const float* __restrict__ cm,
                const float* __restrict__ sigma,
                const float* __restrict__ mu,
                const float* __restrict__ w,
                const float* __restrict__ erev,
                const float* __restrict__ s_sigma,
                const float* __restrict__ s_mu,
                const float* __restrict__ s_w,
                const float* __restrict__ s_erev,
                const float* __restrict__ in_w,
                const float* __restrict__ in_b,
                const float* __restrict__ out_w,
                const float* __restrict__ out_b,
                float* __restrict__ out)
{
    __shared__ __align__(16) float  vsm[2][72];  // v[j] at j + 4*(j>>5)
    __shared__ __align__(8)  float2 lut[1024];   // PWL tanh segments

    const int b    = blockIdx.x;
    const int tid  = threadIdx.x;
    const int lane = tid & 31;
    const int wrp  = tid >> 5;
    const int q    = lane >> 4;
    const int u    = (wrp << 4) | (lane & 15);
    const int rbase = 36 * q;

    // build PWL tanh table (setup only; accurate tanhf at nodes)
    for (int k = tid; k < 1024; k += 128) {
        float x0 = -16.0f + (float)k * (1.0f / 32.0f);
        float t0 = tanhf(x0);
        float t1 = tanhf(x0 + (1.0f / 32.0f));
        float s  = (t1 - t0) * 32.0f;
        lut[k] = make_float2(s, fmaf(-s, x0, t0));
    }
    const float2* lutm512 = lut - 512;

    const float gl   = gleak[u];
    const float cmt  = cm[u] * 6.0f;
    const float glvl = gl * vleak[u];
    const float denc = cmt + gl + 1e-8f;

    // 32 per-(j,u) constants in registers
    float cs[32], cc[32], we[32];
    float Cd = 0.f, Cn = 0.f;
#pragma unroll
    for (int jj = 0; jj < 32; jj++) {
        int j   = 32 * q + jj;
        int idx = j * NU + u;
        float s = 0.5f * sigma[idx];
        cs[jj]  = s;
        cc[jj]  = -mu[idx] * s;
        float wv = 0.5f * w[idx] * erev[idx];
        we[jj]  = wv;
        Cd += fabsf(wv);
        Cn += wv;
    }

    // sensory constants: lane half q handles inputs [3q, 3q+3)
    float ss[3], sc2[3], swe[3], iw[3], ib[3];
    float sCd = 0.f, sCn = 0.f;
#pragma unroll
    for (int i = 0; i < 3; i++) {
        int ii  = 3 * q + i;
        int idx = ii * NU + u;
        float s = 0.5f * s_sigma[idx];
        ss[i]   = s;
        sc2[i]  = -s_mu[idx] * s;
        float wv = 0.5f * s_w[idx] * s_erev[idx];
        swe[i]  = wv;
        sCd += fabsf(wv);
        sCn += wv;
        iw[i] = in_w[ii];
        ib[i] = in_b[ii];
    }

    float ow = 0.f, ob = 0.f;
    if (tid < NM) { ow = out_w[tid]; ob = out_b[tid]; }

    if (q == 0) vsm[0][u + 4 * (u >> 5)] = 0.f;
    float vu = 0.f;

    const float* xb = x + (long long)b * T_LEN * NI + 3 * q;
    float xr0 = xb[0], xr1 = xb[1], xr2 = xb[2];
    float* outp = out + (long long)b * T_LEN * NM;

    __syncthreads();

    for (int t = 0; t < T_LEN; t++) {
        float x0 = xr0, x1 = xr1, x2 = xr2;
        if (t + 1 < T_LEN) {
            const float* xn = xb + (size_t)(t + 1) * NI;
            xr0 = xn[0]; xr1 = xn[1]; xr2 = xn[2];
        }

        // sensory synapses (unbounded args -> MUFU; constant across unfolds)
        float xi0 = fmaf(x0, iw[0], ib[0]);
        float xi1 = fmaf(x1, iw[1], ib[1]);
        float xi2 = fmaf(x2, iw[2], ib[2]);
        float dsa = sCd, nsa = sCn, h;
        h = fast_tanh(fmaf(xi0, ss[0], sc2[0]));
        dsa = fmaf(fabs_bits(swe[0]), h, dsa);  nsa = fmaf(swe[0], h, nsa);
        h = fast_tanh(fmaf(xi1, ss[1], sc2[1]));
        dsa = fmaf(fabs_bits(swe[1]), h, dsa);  nsa = fmaf(swe[1], h, nsa);
        h = fast_tanh(fmaf(xi2, ss[2], sc2[2]));
        dsa = fmaf(fabs_bits(swe[2]), h, dsa);  nsa = fmaf(swe[2], h, nsa);
        dsa += __shfl_xor_sync(0xffffffffu, dsa, 16);
        nsa += __shfl_xor_sync(0xffffffffu, nsa, 16);
        float den_b = denc + dsa;
        float num_b = glvl + nsa;

        // 6 semi-implicit Euler unfolds; per float4 group: 3 MUFU + 1 LUT
#pragma unroll
        for (int k = 0; k < 6; k++) {
            const float4* vr4 =
                reinterpret_cast<const float4*>(&vsm[k & 1][rbase]);
            float an0 = Cn, an1 = 0.f, ad0 = Cd, ad1 = 0.f;
#pragma unroll
            for (int p = 0; p < 8; p++) {
                float4 v4 = vr4[p];                         // LDS.128
                float h0 = fast_tanh(fmaf(v4.x, cs[4*p],   cc[4*p]));
                float h1 = fast_tanh(fmaf(v4.y, cs[4*p+1], cc[4*p+1]));
                float h2 = fast_tanh(fmaf(v4.z, cs[4*p+2], cc[4*p+2]));
                float h3 = lut_tanh(lutm512,
                                    fmaf(v4.w, cs[4*p+3], cc[4*p+3]));
                float w0 = we[4*p],   w1 = we[4*p+1];
                float w2 = we[4*p+2], w3 = we[4*p+3];
                an0 = fmaf(w0, h0, an0);  ad0 = fmaf(fabs_bits(w0), h0, ad0);
                an1 = fmaf(w1, h1, an1);  ad1 = fmaf(fabs_bits(w1), h1, ad1);
                an0 = fmaf(w2, h2, an0);  ad0 = fmaf(fabs_bits(w2), h2, ad0);
                an1 = fmaf(w3, h3, an1);  ad1 = fmaf(fabs_bits(w3), h3, ad1);
            }
            float an = an0 + an1, ad = ad0 + ad1;
            an += __shfl_xor_sync(0xffffffffu, an, 16);
            ad += __shfl_xor_sync(0xffffffffu, ad, 16);
            float num = fmaf(cmt, vu, num_b + an);
            vu = __fdividef(num, den_b + ad);
            if (q == 0) vsm[(k & 1) ^ 1][u + 4 * (u >> 5)] = vu;
            __syncthreads();
        }

        if (tid < NM) outp[(size_t)t * NM + tid] = fmaf(vu, ow, ob);
    }
}

extern "C" void kernel_launch(void* const* d_in, const int* in_sizes, int n_in,
                              void* d_out, int out_size) {
    (void)in_sizes; (void)n_in; (void)out_size;
    ltc_kernel<<<256, 128>>>(
        (const float*)d_in[0],  (const float*)d_in[1],  (const float*)d_in[2],
        (const float*)d_in[3],  (const float*)d_in[4],  (const float*)d_in[5],
        (const float*)d_in[6],  (const float*)d_in[7],  (const float*)d_in[8],
        (const float*)d_in[9],  (const float*)d_in[10], (const float*)d_in[11],
        (const float*)d_in[12], (const float*)d_in[13], (const float*)d_in[14],
        (const float*)d_in[15], (float*)d_out);
}